// round 16
// baseline (speedup 1.0000x reference)
#include <cuda_runtime.h>
#include <math.h>
#include <stdint.h>

// ---------------------------------------------------------------------------
// Revisit_RDLoss: debiased Sinkhorn divergence over softmax rows, 3 pairs.
// SINGLE fused kernel, register-direct MMA fragments, software-pipelined.
// R16 change vs R15: BLOCKED chunk partition. R10..R15 strided chunks by
// nb (block lb read pieces lb, lb+nb, lb+2nb, ... -> ~9400 chip-wide streams
// touching isolated 512B fragments ~50KB apart; HBM page-thrash pinned DRAM
// at 52% while every compute/latency fix was neutral). Now block lb owns the
// CONTIGUOUS range [c0, c0+cnt), so each of its 32 row-streams advances
// sequentially 512B-by-512B (page-local) -- bytes-per-page-activation ~2-4x.
//   Gram phase: Z = [exp(teacher); exp(rec)] (32 x M), G = Z Z^T + row sums.
//     cp.async ring depth 4 x 17KB raw fp32. Iteration s: wait_group 2 ->
//     __syncthreads -> refill slot s+3 -> LDS.64 own fragment floats of
//     stage s -> 10 HMMA on stage s-1's fragments -> exp+pack stage s.
//     Gram symmetry: A fragments reused as B; +2 row-sum MMAs vs ONES.
//     Block partials fp32-atomicAdd'ed into a per-pair global accumulator.
//   Solver phase (last block per pair via atomic ticket): load 1056 floats,
//     self-reset, fp32 C-build, 60-step eps-scaled Sinkhorn with softmin =
//     -eps*log1p(mean_j expm1(u)) via cubic Taylor (|u|<=1e-2).
//     Last pair writes d_out via a global ticket. Counters self-reset.
// ---------------------------------------------------------------------------

#define BROWS 16
#define NTHR  256                 // 8 warps
#define RAWP  544                 // raw row pitch bytes (136 floats)
#define RAWS  (32 * RAWP)         // 17408 B per raw stage
#define SMEMB (4 * RAWS)          // 69632 B dynamic smem per block (ring only)

__device__ float        g_pair[3][1056];      // per-pair accumulators (self-reset)
__device__ float        g_partial[3];
__device__ unsigned int g_pctr[3];            // per-pair completion tickets
__device__ unsigned int g_ctr;                // global ticket; all self-reset

// ---- PTX helpers ------------------------------------------------------------
#define MMA16816(c, a0, a1, a2, a3, b0, b1)                                 \
    asm volatile("mma.sync.aligned.m16n8k16.row.col.f32.bf16.bf16.f32 "     \
                 "{%0,%1,%2,%3}, {%4,%5,%6,%7}, {%8,%9}, {%0,%1,%2,%3};"    \
                 : "+f"((c)[0]), "+f"((c)[1]), "+f"((c)[2]), "+f"((c)[3])   \
                 : "r"(a0), "r"(a1), "r"(a2), "r"(a3), "r"(b0), "r"(b1))

#define CP_ASYNC16(dst, src)                                                \
    asm volatile("cp.async.cg.shared.global [%0], [%1], 16;" :: "r"(dst), "l"(src))
#define CP_COMMIT()  asm volatile("cp.async.commit_group;" ::: "memory")
#define CP_WAIT2()   asm volatile("cp.async.wait_group 2;" ::: "memory")

__device__ __forceinline__ unsigned int pack_bf16x2(float hi, float lo) {
    unsigned int r;
    asm("cvt.rn.bf16x2.f32 %0, %1, %2;" : "=r"(r) : "f"(hi), "f"(lo));
    return r;
}

// load the 8 float2 (16 floats) of this thread's fragment slots for stage s_
#define LOADRAW(s_, raw_)                                                    \
    {                                                                        \
        const char* fb_ = smem_raw + (uint32_t)((s_) & 3) * RAWS + fragbase; \
        _Pragma("unroll")                                                    \
        for (int rr_ = 0; rr_ < 4; rr_++) {                                  \
            raw_[2 * rr_]     = *(const float2*)(fb_ + rr_ * (8 * RAWP));    \
            raw_[2 * rr_ + 1] = *(const float2*)(fb_ + rr_ * (8 * RAWP) + 32); \
        }                                                                    \
    }

// exp + pack 16 floats into fragment registers (layout matches ldmatrix.x4)
#define PACKFRAG(raw_, F0_, F1_)                                             \
    {                                                                        \
        F0_[0] = pack_bf16x2(__expf(raw_[0].y), __expf(raw_[0].x));          \
        F0_[2] = pack_bf16x2(__expf(raw_[1].y), __expf(raw_[1].x));          \
        F0_[1] = pack_bf16x2(__expf(raw_[2].y), __expf(raw_[2].x));          \
        F0_[3] = pack_bf16x2(__expf(raw_[3].y), __expf(raw_[3].x));          \
        F1_[0] = pack_bf16x2(__expf(raw_[4].y), __expf(raw_[4].x));          \
        F1_[2] = pack_bf16x2(__expf(raw_[5].y), __expf(raw_[5].x));          \
        F1_[1] = pack_bf16x2(__expf(raw_[6].y), __expf(raw_[6].x));          \
        F1_[3] = pack_bf16x2(__expf(raw_[7].y), __expf(raw_[7].x));          \
    }

#define MMA_ALL(F0_, F1_)                                                    \
    {                                                                        \
        MMA16816(acc[0], F0_[0], F0_[1], F0_[2], F0_[3], F0_[0], F0_[2]);    \
        MMA16816(acc[1], F0_[0], F0_[1], F0_[2], F0_[3], F0_[1], F0_[3]);    \
        MMA16816(acc[2], F0_[0], F0_[1], F0_[2], F0_[3], F1_[0], F1_[2]);    \
        MMA16816(acc[3], F0_[0], F0_[1], F0_[2], F0_[3], F1_[1], F1_[3]);    \
        MMA16816(acc[4], F1_[0], F1_[1], F1_[2], F1_[3], F0_[0], F0_[2]);    \
        MMA16816(acc[5], F1_[0], F1_[1], F1_[2], F1_[3], F0_[1], F0_[3]);    \
        MMA16816(acc[6], F1_[0], F1_[1], F1_[2], F1_[3], F1_[0], F1_[2]);    \
        MMA16816(acc[7], F1_[0], F1_[1], F1_[2], F1_[3], F1_[1], F1_[3]);    \
        MMA16816(accS[0], F0_[0], F0_[1], F0_[2], F0_[3], ONES, ONES);       \
        MMA16816(accS[1], F1_[0], F1_[1], F1_[2], F1_[3], ONES, ONES);       \
    }

// solver smem overlay (lives in the dynamic smem after gram is done)
struct SolverSmem {
    float sG[1024];           // reduced gram (row-major 32x32)
    float sS[32];             // row sums
    float sIS[32];            // 1/S
    float sA2[32];            // ||row||^2 normalized
    float C[4][16][17];       // 0:Cxy 1:CxyT 2:Cxx 3:Cyy (padded rows)
    float pot[2][4][16];
    float fin[4][16];
    float epss[60];
    unsigned int last_flag;
};

__global__ void __launch_bounds__(NTHR, 2)
fused_kernel(const float* __restrict__ T0, const float* __restrict__ R0, int M0, int nb0,
             const float* __restrict__ T1, const float* __restrict__ R1, int M1, int nb1,
             const float* __restrict__ T2, const float* __restrict__ R2, int M2, int nb2,
             float* __restrict__ out)
{
    extern __shared__ __align__(16) char smem_raw[];
    const uint32_t sbase = (uint32_t)__cvta_generic_to_shared(smem_raw);

    const int tid  = threadIdx.x;
    const int wid  = tid >> 5;
    const int lane = tid & 31;

    // --- pick pair ---
    const float *T, *R; int M, lb, nb, pair;
    int b = blockIdx.x;
    if (b < nb0)            { T = T0; R = R0; M = M0; lb = b;             nb = nb0; pair = 0; }
    else if (b < nb0 + nb1) { T = T1; R = R1; M = M1; lb = b - nb0;       nb = nb1; pair = 1; }
    else                    { T = T2; R = R2; M = M2; lb = b - nb0 - nb1; nb = nb2; pair = 2; }
    const int cntb = nb;

    // =========================== GRAM PHASE =================================
    // BLOCKED chunk partition: block lb owns contiguous chunks [c0, c0+cnt).
    const int niter = M >> 7;                       // TKI = 128
    const int per  = niter / nb;
    const int rem2 = niter % nb;
    const int c0   = lb * per + (lb < rem2 ? lb : rem2);
    const int cnt  = per + (lb < rem2 ? 1 : 0);

    // cp.async loader mapping: thread covers one 32-float row slice (coalesced)
    const int lrow = ((wid >> 1) << 3) + ((wid & 1) << 1)
                   + ((lane >> 3) & 1) + ((lane >> 4) << 2);
    const int c4   = lane & 7;
    const float* rbase = (lrow < BROWS) ? (T + (size_t)lrow * (size_t)M)
                                        : (R + (size_t)(lrow - BROWS) * (size_t)M);
    const float4* g4 = (const float4*)rbase + c4;
    const uint32_t rawoff = (uint32_t)(lrow * RAWP + c4 * 16);

    // fragment read base: rows {fr, fr+8, fr+16, fr+24}, k pairs at
    // wid*64 + (lane&3)*8 bytes, +0 and +32
    const int fr = lane >> 2;
    const uint32_t fragbase = (uint32_t)(fr * RAWP + wid * 64 + (lane & 3) * 8);

    float acc[8][4];
#pragma unroll
    for (int i = 0; i < 8; i++)
#pragma unroll
        for (int jj = 0; jj < 4; jj++) acc[i][jj] = 0.f;
    float accS[2][4];                   // row-sum MMA accumulators
#pragma unroll
    for (int i = 0; i < 2; i++)
#pragma unroll
        for (int jj = 0; jj < 4; jj++) accS[i][jj] = 0.f;

    const unsigned int ONES = 0x3F803F80u;          // bf16x2 (1.0, 1.0)

    auto issue = [&](int s2) {
        if (s2 < cnt) {
            uint32_t dst = sbase + (uint32_t)(s2 & 3) * RAWS + rawoff;
            const float4* src = g4 + (size_t)(c0 + s2) * 32;
#pragma unroll
            for (int t = 0; t < 4; t++)
                CP_ASYNC16(dst + 128u * t, src + 8 * t);
        }
        CP_COMMIT();
    };

    // prologue: fill 3 stages of the 4-slot ring
    issue(0);
    issue(1);
    issue(2);

    uint32_t LA0[4], LA1[4], LB0[4], LB1[4];

    // stage 0: produce first fragment set (no MMA yet)
    {
        CP_WAIT2();
        __syncthreads();
        issue(3);
        float2 raw[8];
        LOADRAW(0, raw);
        PACKFRAG(raw, LA0, LA1);
    }

    int s = 1;
    for (; s + 1 < cnt; s += 2) {
        {   // stage s: MMA on stage s-1 (set A), produce set B
            CP_WAIT2();
            __syncthreads();
            issue(s + 3);
            float2 raw[8];
            LOADRAW(s, raw);
            MMA_ALL(LA0, LA1);
            PACKFRAG(raw, LB0, LB1);
        }
        {   // stage s+1: MMA on stage s (set B), produce set A
            CP_WAIT2();
            __syncthreads();
            issue(s + 4);
            float2 raw[8];
            LOADRAW(s + 1, raw);
            MMA_ALL(LB0, LB1);
            PACKFRAG(raw, LA0, LA1);
        }
    }
    if (s < cnt) {      // one leftover stage: consume A, produce+flush B
        CP_WAIT2();
        __syncthreads();
        issue(s + 3);
        float2 raw[8];
        LOADRAW(s, raw);
        MMA_ALL(LA0, LA1);
        PACKFRAG(raw, LB0, LB1);
        MMA_ALL(LB0, LB1);
    } else {            // even count: flush A
        MMA_ALL(LA0, LA1);
    }

    // --- block combine (reuse raw smem), then global fp32 atomics ---
    __syncthreads();
    {
        float* gc = (float*)smem_raw;               // [32][33]
        float* rs = gc + 32 * 33;                   // [32]
        for (int i = tid; i < 32 * 33 + 32; i += NTHR) gc[i] = 0.f;
        __syncthreads();

        const int fc = 2 * (lane & 3);
#pragma unroll
        for (int mi = 0; mi < 2; mi++)
#pragma unroll
            for (int nt = 0; nt < 4; nt++) {
                float* a = acc[mi * 4 + nt];
                int r = mi * 16 + fr;
                int c = nt * 8 + fc;
                atomicAdd(&gc[r * 33 + c],           a[0]);
                atomicAdd(&gc[r * 33 + c + 1],       a[1]);
                atomicAdd(&gc[(r + 8) * 33 + c],     a[2]);
                atomicAdd(&gc[(r + 8) * 33 + c + 1], a[3]);
            }
        // row sums live in column 0 of the ones-MMA result (all columns equal)
        if ((lane & 3) == 0) {
            atomicAdd(&rs[fr],      accS[0][0]);
            atomicAdd(&rs[fr + 8],  accS[0][2]);
            atomicAdd(&rs[fr + 16], accS[1][0]);
            atomicAdd(&rs[fr + 24], accS[1][2]);
        }
        __syncthreads();

        // distributed reduction: fp32 atomics into the per-pair accumulator
        for (int i = tid; i < 1056; i += NTHR) {
            float v2 = (i < 1024) ? gc[(i >> 5) * 33 + (i & 31)] : rs[i - 1024];
            atomicAdd(&g_pair[pair][i], v2);
        }
    }

    // --- per-pair ticket: only the last block continues ---
    SolverSmem* ss = (SolverSmem*)smem_raw;
    __threadfence();
    __syncthreads();
    if (tid == 0) {
        unsigned int tk = atomicAdd(&g_pctr[pair], 1);
        ss->last_flag = (tk == (unsigned int)(cntb - 1));
        if (ss->last_flag) g_pctr[pair] = 0;     // self-reset
    }
    __syncthreads();
    if (!ss->last_flag) return;
    __threadfence();                 // acquire: other blocks' atomics visible

    // =========================== SOLVER PHASE ================================
    // load the 1056-float accumulator, self-reset for the next graph replay
    for (int i = tid; i < 1056; i += NTHR) {
        float v2 = g_pair[pair][i];
        g_pair[pair][i] = 0.f;
        if (i < 1024) ss->sG[i] = v2;
        else          ss->sS[i - 1024] = v2;
    }
    if (tid < 60)
        ss->epss[tid] = fmaxf(exp2f((float)tid * -0.14800216f), 0.0025f);
    if (tid < 64) ss->pot[0][tid >> 4][tid & 15] = 0.f;
    __syncthreads();

    if (tid < 32) {
        float inv = 1.0f / ss->sS[tid];
        ss->sIS[tid] = inv;
        ss->sA2[tid] = (ss->sG[tid * 32 + tid] * inv) * inv;
    }
    __syncthreads();

    {
        int ii = tid >> 4, jj = tid & 15;
        float ISi  = ss->sIS[ii],      ISj  = ss->sIS[jj];
        float ISyi = ss->sIS[16 + ii], ISyj = ss->sIS[16 + jj];
        float a2i = ss->sA2[ii], a2j = ss->sA2[jj];
        float b2i = ss->sA2[16 + ii], b2j = ss->sA2[16 + jj];
        int lo = min(ii, jj), hi = max(ii, jj);
        float cxy = fmaf(-ss->sG[ii * 32 + 16 + jj] * ISi, ISyj, 0.5f * (a2i + b2j));
        float cxx = 0.5f * (a2i + a2j) - (ss->sG[lo * 32 + hi] * ISi) * ISj;
        float cyy = 0.5f * (b2i + b2j) - (ss->sG[(16 + lo) * 32 + 16 + hi] * ISyi) * ISyj;
        if (ii == jj) { cxx = 0.f; cyy = 0.f; }     // exact diagonal
        ss->C[0][ii][jj] = cxy;
        ss->C[1][jj][ii] = cxy;                     // transposed copy
        ss->C[2][ii][jj] = cxx;
        ss->C[3][ii][jj] = cyy;
    }
    __syncthreads();

    {
        const int q  = tid >> 6;
        const int i  = (tid >> 2) & 15;
        const int jg = tid & 3;
        const int hq = (q == 0) ? 1 : ((q == 1) ? 0 : q);
        const float* Crow = ss->C[q][i];

        int cur = 0;
        for (int s2 = 0; s2 < 60; s2++) {
            float eps = ss->epss[s2];
            float inv_eps = 1.0f / eps;
            const float* hp = ss->pot[cur][hq];
            float old = ss->pot[cur][q][i];
            float t = 0.f;
#pragma unroll
            for (int it = 0; it < 4; it++) {
                int jj = jg * 4 + it;
                float u = (hp[jj] - Crow[jj]) * inv_eps;
                t += u * fmaf(u, fmaf(u, 0.16666667f, 0.5f), 1.0f);   // expm1
            }
            t += __shfl_xor_sync(0xffffffffu, t, 1);
            t += __shfl_xor_sync(0xffffffffu, t, 2);
            if (jg == 0) {
                float m = t * 0.0625f;
                float l = m * fmaf(m, fmaf(m, 0.33333333f, -0.5f), 1.0f);  // log1p
                ss->pot[cur ^ 1][q][i] = 0.5f * (old - eps * l);
            }
            __syncthreads();
            cur ^= 1;
        }

        {
            const float eps = 0.0025f;
            const float inv_eps = 1.0f / eps;
            const float* hp = ss->pot[cur][hq];
            float t = 0.f;
#pragma unroll
            for (int it = 0; it < 4; it++) {
                int jj = jg * 4 + it;
                float u = (hp[jj] - Crow[jj]) * inv_eps;
                t += u * fmaf(u, fmaf(u, 0.16666667f, 0.5f), 1.0f);
            }
            t += __shfl_xor_sync(0xffffffffu, t, 1);
            t += __shfl_xor_sync(0xffffffffu, t, 2);
            if (jg == 0) {
                float m = t * 0.0625f;
                float l = m * fmaf(m, fmaf(m, 0.33333333f, -0.5f), 1.0f);
                ss->fin[q][i] = -eps * l;
            }
            __syncthreads();
        }
    }

    if (tid == 0) {
        float acc2 = 0.f;
#pragma unroll
        for (int ii = 0; ii < 16; ii++)
            acc2 += (ss->fin[0][ii] - ss->fin[2][ii])
                  + (ss->fin[1][ii] - ss->fin[3][ii]);
        g_partial[pair] = acc2 / 48.0f;      // mean over 16, /3 pairs
        __threadfence();
        unsigned int tk = atomicAdd(&g_ctr, 1);
        if (tk == 2) {
            out[0] = g_partial[0] + g_partial[1] + g_partial[2];
            g_ctr = 0;                       // self-reset for graph replay
        }
    }
}

// ---------------------------------------------------------------------------
extern "C" void kernel_launch(void* const* d_in, const int* in_sizes, int n_in,
                              void* d_out, int out_size)
{
    (void)out_size;
    // Pair the 6 inputs by element count (divergence is symmetric in (x, y)).
    int idx[6] = {0, 1, 2, 3, 4, 5};
    int n = (n_in < 6) ? n_in : 6;
    for (int a = 0; a < n; a++)
        for (int b = a + 1; b < n; b++)
            if (in_sizes[idx[b]] > in_sizes[idx[a]]) {
                int tmp = idx[a]; idx[a] = idx[b]; idx[b] = tmp;
            }

    const float* T[3]; const float* R[3]; int M[3]; int nb[3];
    for (int p = 0; p < 3; p++) {
        T[p] = (const float*)d_in[idx[2 * p]];
        R[p] = (const float*)d_in[idx[2 * p + 1]];
        M[p] = in_sizes[idx[2 * p]] / BROWS;
        int iters = M[p] >> 7;                 // TKI = 128
        nb[p] = (iters + 48) / 49;             // ~49 iters/block, ~294 blocks (2/SM)
        if (nb[p] < 1) nb[p] = 1;
        if (nb[p] > iters) nb[p] = iters;
    }

    static int smem_set = 0;
    if (!smem_set) {
        cudaFuncSetAttribute(fused_kernel,
                             cudaFuncAttributeMaxDynamicSharedMemorySize, SMEMB);
        smem_set = 1;
    }

    fused_kernel<<<nb[0] + nb[1] + nb[2], NTHR, SMEMB>>>(
        T[0], R[0], M[0], nb[0],
        T[1], R[1], M[1], nb[1],
        T[2], R[2], M[2], nb[2],
        (float*)d_out);
}